// round 1
// baseline (speedup 1.0000x reference)
#include <cuda_runtime.h>
#include <math.h>

#define LAYERS 30
#define B_SZ 4
#define TLEN 32000
#define TT 64
#define NTILES (B_SZ * (TLEN / TT))   /* 2000 */
#define CH 64
#define GCH 128
#define CCH 80

/* packed per-layer weight blob (floats), all matrices transposed to [c][o] */
#define LAYER_WSZ 35072
#define OFF_WT1   8192
#define OFF_WTC   16384
#define OFF_WZ    26624
#define OFF_BCONV 34816
#define OFF_BSK   34944
#define OFF_BOUT  35008

/* scratch (device globals: allocation-free rule) */
__device__ float g_h[2][B_SZ * CH * TLEN];      /* ping-pong residual */
__device__ float g_skips[B_SZ * CH * TLEN];
__device__ float g_c1[B_SZ * CCH * 400];
__device__ float g_c2[B_SZ * CCH * 4000];
__device__ float g_cup[B_SZ * CCH * TLEN];
__device__ float g_wt[LAYERS * LAYER_WSZ];
__device__ float g_wfirstT[256 * 64];
__device__ float g_wl1T[64 * 64];
__device__ float g_wl2T[64 * 256];

__device__ __forceinline__ float sig_f(float v) {
    return __fdividef(1.f, 1.f + __expf(-v));
}
__device__ __forceinline__ float tanh_f(float v) {
    return __fdividef(2.f, 1.f + __expf(-2.f * v)) - 1.f;
}

/* ------------------- weight prep: transpose/pack, coalesced layer loads ----- */
__global__ void prep_layers_kernel(const float* __restrict__ conv_w,
                                   const float* __restrict__ conv_b,
                                   const float* __restrict__ cond_w,
                                   const float* __restrict__ out_w,
                                   const float* __restrict__ out_b,
                                   const float* __restrict__ skip_w,
                                   const float* __restrict__ skip_b) {
    int idx = blockIdx.x * blockDim.x + threadIdx.x;
    if (idx >= LAYERS * LAYER_WSZ) return;
    int l = idx / LAYER_WSZ;
    int j = idx % LAYER_WSZ;
    float v;
    if (j < OFF_WT1) {                       /* wt0[c][o] : delayed tap */
        int c = j >> 7, o = j & 127;
        v = conv_w[((l * 128 + o) * 64 + c) * 2 + 0];
    } else if (j < OFF_WTC) {                /* wt1[c][o] : current tap */
        int jj = j - OFF_WT1; int c = jj >> 7, o = jj & 127;
        v = conv_w[((l * 128 + o) * 64 + c) * 2 + 1];
    } else if (j < OFF_WZ) {                 /* wtc[c][o] : cond */
        int jj = j - OFF_WTC; int c = jj >> 7, o = jj & 127;
        v = cond_w[(l * 128 + o) * 80 + c];
    } else if (j < OFF_BCONV) {              /* wz[c][o2] : skip(0..63)|out(64..127) */
        int jj = j - OFF_WZ; int c = jj >> 7, o2 = jj & 127;
        v = (o2 < 64) ? skip_w[(l * 64 + o2) * 64 + c]
                      : out_w[(l * 64 + (o2 - 64)) * 64 + c];
    } else if (j < OFF_BSK) {
        v = conv_b[l * 128 + (j - OFF_BCONV)];
    } else if (j < OFF_BOUT) {
        v = skip_b[l * 64 + (j - OFF_BSK)];
    } else {
        v = out_b[l * 64 + (j - OFF_BOUT)];
    }
    g_wt[idx] = v;
}

__global__ void prep_firstlast_kernel(const float* __restrict__ first_w,
                                      const float* __restrict__ last1_w,
                                      const float* __restrict__ last2_w) {
    int idx = blockIdx.x * blockDim.x + threadIdx.x;
    if (idx < 16384) {                                   /* firstT[c][o], c<256,o<64 */
        int c = idx >> 6, o = idx & 63;
        g_wfirstT[idx] = first_w[o * 256 + c];
    } else if (idx < 16384 + 4096) {                     /* l1T[c][o] 64x64 */
        int jj = idx - 16384; int c = jj >> 6, o = jj & 63;
        g_wl1T[jj] = last1_w[o * 64 + c];
    } else if (idx < 16384 + 4096 + 16384) {             /* l2T[c][o] 64x256 */
        int jj = idx - 16384 - 4096; int c = jj >> 8, o = jj & 255;
        g_wl2T[jj] = last2_w[o * 64 + c];
    }
}

/* ------------------- conditioning network ---------------------------------- */
__global__ void convin_kernel(const float* __restrict__ cin,
                              const float* __restrict__ w) {
    int idx = blockIdx.x * blockDim.x + threadIdx.x;
    if (idx >= B_SZ * CCH * 400) return;
    int f = idx % 400;
    int o = (idx / 400) % CCH;
    int b = idx / (400 * CCH);
    const float* src = cin + (b * CCH) * 400 + f;
    float acc = 0.f;
#pragma unroll 8
    for (int c = 0; c < 80; ++c)
        acc += __ldg(&w[o * 80 + c]) * src[c * 400];
    g_c1[idx] = acc;
}

/* nearest-repeat by `scale` then depthwise conv (K=2*scale+1, zero pad scale) */
__global__ void upsample_kernel(const float* __restrict__ src,
                                const float* __restrict__ w,
                                float* __restrict__ dst,
                                int srcT, int dstT, int scale, int K) {
    int idx = blockIdx.x * blockDim.x + threadIdx.x;
    if (idx >= B_SZ * CCH * dstT) return;
    int t = idx % dstT;
    int ch = (idx / dstT) % CCH;
    int b = idx / (dstT * CCH);
    const float* s = src + (b * CCH + ch) * srcT;
    int base = t - scale;
    float acc = 0.f;
    for (int j = 0; j < K; ++j) {
        int u = base + j;
        if (u >= 0 && u < dstT) acc += __ldg(&w[j]) * s[u / scale];
    }
    dst[idx] = acc;
}

/* ------------------- first 1x1 conv: h = first_w @ x + b ------------------- */
__global__ void first_kernel(const float* __restrict__ x,
                             const float* __restrict__ first_b) {
    extern __shared__ float sm[];
    float* xs = sm;            /* [256][64] */
    float* wf = sm + 16384;    /* wfT[c][o] 256x64 */
    for (int i = threadIdx.x; i < 16384 / 4; i += blockDim.x)
        ((float4*)wf)[i] = ((const float4*)g_wfirstT)[i];

    int to = threadIdx.x & 15, oo = threadIdx.x >> 4;
    int tb = to * 4, ob = oo * 4;

    for (int tile = blockIdx.x; tile < NTILES; tile += gridDim.x) {
        int b = tile / (TLEN / TT);
        int t0 = (tile % (TLEN / TT)) * TT;
        __syncthreads();
        const float* xb = x + (size_t)b * 256 * TLEN;
        for (int i = threadIdx.x; i < 256 * (TT / 4); i += blockDim.x) {
            int c = i / (TT / 4), q = i % (TT / 4);
            ((float4*)xs)[c * (TT / 4) + q] =
                *(const float4*)&xb[c * TLEN + t0 + q * 4];
        }
        __syncthreads();

        float acc[4][4];
#pragma unroll
        for (int oi = 0; oi < 4; ++oi) {
            float bv = first_b[ob + oi];
#pragma unroll
            for (int ti = 0; ti < 4; ++ti) acc[oi][ti] = bv;
        }
#pragma unroll 4
        for (int c = 0; c < 256; ++c) {
            float4 xv4 = *(const float4*)(xs + c * TT + tb);
            float4 wv4 = *(const float4*)(wf + c * 64 + ob);
            float xv[4] = {xv4.x, xv4.y, xv4.z, xv4.w};
            float wv[4] = {wv4.x, wv4.y, wv4.z, wv4.w};
#pragma unroll
            for (int oi = 0; oi < 4; ++oi)
#pragma unroll
                for (int ti = 0; ti < 4; ++ti)
                    acc[oi][ti] += wv[oi] * xv[ti];
        }
        float* hb = g_h[0] + (size_t)b * CH * TLEN;
#pragma unroll
        for (int oi = 0; oi < 4; ++oi) {
            float4 v; v.x = acc[oi][0]; v.y = acc[oi][1];
            v.z = acc[oi][2]; v.w = acc[oi][3];
            *(float4*)&hb[(ob + oi) * TLEN + t0 + tb] = v;
        }
    }
}

/* ------------------- fused WaveNet residual layer -------------------------- */
__global__ void layer_kernel(int l, int d, int hin, int first_layer) {
    extern __shared__ float sm[];
    float* sw = sm;                          /* 35072 packed weights */
    float* sh_cur = sm + LAYER_WSZ;          /* [64][TT] */
    float* sh_del = sh_cur + CH * TT;        /* [64][TT] */
    float* sc = sh_del + CH * TT;            /* [80][TT] */
    float* sg = sc + CCH * TT;               /* [128][TT]; rows 0..63 reused for z */

    const float* wt0 = sw;
    const float* wt1 = sw + OFF_WT1;
    const float* wtc = sw + OFF_WTC;
    const float* wz  = sw + OFF_WZ;
    const float* bconv = sw + OFF_BCONV;
    const float* bsk = sw + OFF_BSK;
    const float* bout = sw + OFF_BOUT;

    const float* wsrc = g_wt + (size_t)l * LAYER_WSZ;
    for (int i = threadIdx.x; i < LAYER_WSZ / 4; i += blockDim.x)
        ((float4*)sw)[i] = ((const float4*)wsrc)[i];

    const float* h_in = g_h[hin];
    float* h_out = g_h[hin ^ 1];

    int to = threadIdx.x & 15;   /* 16 time groups of 4 */
    int oo = threadIdx.x >> 4;   /* 16 out groups of 8  */
    int tb = to * 4, ob = oo * 8;

    for (int tile = blockIdx.x; tile < NTILES; tile += gridDim.x) {
        int b = tile / (TLEN / TT);
        int t0 = (tile % (TLEN / TT)) * TT;
        __syncthreads();   /* protect smem from previous iteration readers */

        const float* hb = h_in + (size_t)b * CH * TLEN;
        for (int i = threadIdx.x; i < CH * (TT / 4); i += blockDim.x) {
            int c = i / (TT / 4), q = i % (TT / 4);
            ((float4*)sh_cur)[c * (TT / 4) + q] =
                *(const float4*)&hb[c * TLEN + t0 + q * 4];
        }
        for (int i = threadIdx.x; i < CH * TT; i += blockDim.x) {
            int c = i >> 6, tt = i & 63;
            int t = t0 + tt - d;
            sh_del[c * TT + tt] = (t >= 0) ? hb[c * TLEN + t] : 0.f;
        }
        const float* cb = g_cup + (size_t)b * CCH * TLEN;
        for (int i = threadIdx.x; i < CCH * (TT / 4); i += blockDim.x) {
            int c = i / (TT / 4), q = i % (TT / 4);
            ((float4*)sc)[c * (TT / 4) + q] =
                *(const float4*)&cb[c * TLEN + t0 + q * 4];
        }
        __syncthreads();

        /* ---- gate GEMM: g[128][TT] = W0*h(t-d) + W1*h(t) + Wc*c + b ---- */
        float acc[8][4];
#pragma unroll
        for (int oi = 0; oi < 8; ++oi) {
            float bv = bconv[ob + oi];
#pragma unroll
            for (int ti = 0; ti < 4; ++ti) acc[oi][ti] = bv;
        }
#pragma unroll 2
        for (int c = 0; c < 64; ++c) {
            float4 hd4 = *(const float4*)(sh_del + c * TT + tb);
            float4 hc4 = *(const float4*)(sh_cur + c * TT + tb);
            float4 wa0 = *(const float4*)(wt0 + c * 128 + ob);
            float4 wb0 = *(const float4*)(wt0 + c * 128 + ob + 4);
            float4 wa1 = *(const float4*)(wt1 + c * 128 + ob);
            float4 wb1 = *(const float4*)(wt1 + c * 128 + ob + 4);
            float w0v[8] = {wa0.x, wa0.y, wa0.z, wa0.w, wb0.x, wb0.y, wb0.z, wb0.w};
            float w1v[8] = {wa1.x, wa1.y, wa1.z, wa1.w, wb1.x, wb1.y, wb1.z, wb1.w};
            float hdv[4] = {hd4.x, hd4.y, hd4.z, hd4.w};
            float hcv[4] = {hc4.x, hc4.y, hc4.z, hc4.w};
#pragma unroll
            for (int oi = 0; oi < 8; ++oi)
#pragma unroll
                for (int ti = 0; ti < 4; ++ti) {
                    acc[oi][ti] += w0v[oi] * hdv[ti];
                    acc[oi][ti] += w1v[oi] * hcv[ti];
                }
        }
#pragma unroll 2
        for (int c = 0; c < 80; ++c) {
            float4 cv4 = *(const float4*)(sc + c * TT + tb);
            float4 wa = *(const float4*)(wtc + c * 128 + ob);
            float4 wb = *(const float4*)(wtc + c * 128 + ob + 4);
            float wv[8] = {wa.x, wa.y, wa.z, wa.w, wb.x, wb.y, wb.z, wb.w};
            float cv[4] = {cv4.x, cv4.y, cv4.z, cv4.w};
#pragma unroll
            for (int oi = 0; oi < 8; ++oi)
#pragma unroll
                for (int ti = 0; ti < 4; ++ti)
                    acc[oi][ti] += wv[oi] * cv[ti];
        }
#pragma unroll
        for (int oi = 0; oi < 8; ++oi) {
            float4 v; v.x = acc[oi][0]; v.y = acc[oi][1];
            v.z = acc[oi][2]; v.w = acc[oi][3];
            *(float4*)(sg + (ob + oi) * TT + tb) = v;
        }
        __syncthreads();

        /* ---- z = tanh(a) * sigmoid(b), in place over rows 0..63 ---- */
        {
            int o = threadIdx.x >> 2;
            int ts = (threadIdx.x & 3) * 16;
#pragma unroll
            for (int k = 0; k < 16; k += 4) {
                float4 a4 = *(const float4*)(sg + o * TT + ts + k);
                float4 b4 = *(const float4*)(sg + (o + 64) * TT + ts + k);
                float4 z4;
                z4.x = tanh_f(a4.x) * sig_f(b4.x);
                z4.y = tanh_f(a4.y) * sig_f(b4.y);
                z4.z = tanh_f(a4.z) * sig_f(b4.z);
                z4.w = tanh_f(a4.w) * sig_f(b4.w);
                *(float4*)(sg + o * TT + ts + k) = z4;
            }
        }
        __syncthreads();

        /* ---- skip/out GEMM: [skip;out][128] x z[64] ---- */
#pragma unroll
        for (int oi = 0; oi < 8; ++oi) {
            int o2 = ob + oi;
            float bv = (o2 < 64) ? bsk[o2] : bout[o2 - 64];
#pragma unroll
            for (int ti = 0; ti < 4; ++ti) acc[oi][ti] = bv;
        }
#pragma unroll 2
        for (int c = 0; c < 64; ++c) {
            float4 zv4 = *(const float4*)(sg + c * TT + tb);
            float4 wa = *(const float4*)(wz + c * 128 + ob);
            float4 wb = *(const float4*)(wz + c * 128 + ob + 4);
            float wv[8] = {wa.x, wa.y, wa.z, wa.w, wb.x, wb.y, wb.z, wb.w};
            float zv[4] = {zv4.x, zv4.y, zv4.z, zv4.w};
#pragma unroll
            for (int oi = 0; oi < 8; ++oi)
#pragma unroll
                for (int ti = 0; ti < 4; ++ti)
                    acc[oi][ti] += wv[oi] * zv[ti];
        }

        if (ob < 64) {  /* skip accumulation */
            float* skb = g_skips + (size_t)b * CH * TLEN;
#pragma unroll
            for (int oi = 0; oi < 8; ++oi) {
                float* p = skb + (ob + oi) * TLEN + t0 + tb;
                float4 v; v.x = acc[oi][0]; v.y = acc[oi][1];
                v.z = acc[oi][2]; v.w = acc[oi][3];
                if (!first_layer) {
                    float4 o4 = *(const float4*)p;
                    v.x += o4.x; v.y += o4.y; v.z += o4.z; v.w += o4.w;
                }
                *(float4*)p = v;
            }
        } else {        /* residual update h_out = h_in + out */
            float* hob = h_out + (size_t)b * CH * TLEN;
#pragma unroll
            for (int oi = 0; oi < 8; ++oi) {
                int o = ob - 64 + oi;
                float4 hc4 = *(const float4*)(sh_cur + o * TT + tb);
                float4 v; v.x = acc[oi][0] + hc4.x; v.y = acc[oi][1] + hc4.y;
                v.z = acc[oi][2] + hc4.z; v.w = acc[oi][3] + hc4.w;
                *(float4*)&hob[o * TLEN + t0 + tb] = v;
            }
        }
    }
}

/* ------------------- last: relu -> 1x1(64) -> relu -> 1x1(256) ------------- */
__global__ void last_kernel(const float* __restrict__ l1b,
                            const float* __restrict__ l2b,
                            float* __restrict__ out) {
    extern __shared__ float sm[];
    float* w1 = sm;             /* 64x64  l1T[c][o] */
    float* w2 = sm + 4096;      /* 64x256 l2T[c][o] */
    float* sk = sm + 20480;     /* [64][TT] */
    float* o1 = sm + 24576;     /* [64][TT] */

    for (int i = threadIdx.x; i < 4096 / 4; i += blockDim.x)
        ((float4*)w1)[i] = ((const float4*)g_wl1T)[i];
    for (int i = threadIdx.x; i < 16384 / 4; i += blockDim.x)
        ((float4*)w2)[i] = ((const float4*)g_wl2T)[i];

    int to = threadIdx.x & 15, oo = threadIdx.x >> 4;
    int tb = to * 4;

    for (int tile = blockIdx.x; tile < NTILES; tile += gridDim.x) {
        int b = tile / (TLEN / TT);
        int t0 = (tile % (TLEN / TT)) * TT;
        __syncthreads();
        const float* skb = g_skips + (size_t)b * CH * TLEN;
        for (int i = threadIdx.x; i < CH * (TT / 4); i += blockDim.x) {
            int c = i / (TT / 4), q = i % (TT / 4);
            float4 v = *(const float4*)&skb[c * TLEN + t0 + q * 4];
            v.x = fmaxf(v.x, 0.f); v.y = fmaxf(v.y, 0.f);
            v.z = fmaxf(v.z, 0.f); v.w = fmaxf(v.w, 0.f);
            ((float4*)sk)[c * (TT / 4) + q] = v;
        }
        __syncthreads();

        /* GEMM1: 64x64, relu */
        {
            int ob = oo * 4;
            float acc[4][4];
#pragma unroll
            for (int oi = 0; oi < 4; ++oi) {
                float bv = l1b[ob + oi];
#pragma unroll
                for (int ti = 0; ti < 4; ++ti) acc[oi][ti] = bv;
            }
#pragma unroll 4
            for (int c = 0; c < 64; ++c) {
                float4 xv4 = *(const float4*)(sk + c * TT + tb);
                float4 wv4 = *(const float4*)(w1 + c * 64 + ob);
                float xv[4] = {xv4.x, xv4.y, xv4.z, xv4.w};
                float wv[4] = {wv4.x, wv4.y, wv4.z, wv4.w};
#pragma unroll
                for (int oi = 0; oi < 4; ++oi)
#pragma unroll
                    for (int ti = 0; ti < 4; ++ti)
                        acc[oi][ti] += wv[oi] * xv[ti];
            }
#pragma unroll
            for (int oi = 0; oi < 4; ++oi) {
                float4 v;
                v.x = fmaxf(acc[oi][0], 0.f); v.y = fmaxf(acc[oi][1], 0.f);
                v.z = fmaxf(acc[oi][2], 0.f); v.w = fmaxf(acc[oi][3], 0.f);
                *(float4*)(o1 + (ob + oi) * TT + tb) = v;
            }
        }
        __syncthreads();

        /* GEMM2: 256x64, two halves of 128 outputs */
        float* ob_out = out + (size_t)b * 256 * TLEN;
#pragma unroll
        for (int half = 0; half < 2; ++half) {
            int ob2 = half * 128 + oo * 8;
            float acc[8][4];
#pragma unroll
            for (int oi = 0; oi < 8; ++oi) {
                float bv = l2b[ob2 + oi];
#pragma unroll
                for (int ti = 0; ti < 4; ++ti) acc[oi][ti] = bv;
            }
#pragma unroll 2
            for (int c = 0; c < 64; ++c) {
                float4 zv4 = *(const float4*)(o1 + c * TT + tb);
                float4 wa = *(const float4*)(w2 + c * 256 + ob2);
                float4 wb = *(const float4*)(w2 + c * 256 + ob2 + 4);
                float wv[8] = {wa.x, wa.y, wa.z, wa.w, wb.x, wb.y, wb.z, wb.w};
                float zv[4] = {zv4.x, zv4.y, zv4.z, zv4.w};
#pragma unroll
                for (int oi = 0; oi < 8; ++oi)
#pragma unroll
                    for (int ti = 0; ti < 4; ++ti)
                        acc[oi][ti] += wv[oi] * zv[ti];
            }
#pragma unroll
            for (int oi = 0; oi < 8; ++oi) {
                float4 v; v.x = acc[oi][0]; v.y = acc[oi][1];
                v.z = acc[oi][2]; v.w = acc[oi][3];
                *(float4*)&ob_out[(ob2 + oi) * TLEN + t0 + tb] = v;
            }
        }
    }
}

/* --------------------------------------------------------------------------- */
extern "C" void kernel_launch(void* const* d_in, const int* in_sizes, int n_in,
                              void* d_out, int out_size) {
    const float* x        = (const float*)d_in[0];
    const float* c        = (const float*)d_in[1];
    const float* first_w  = (const float*)d_in[2];
    const float* first_b  = (const float*)d_in[3];
    const float* conv_w   = (const float*)d_in[4];
    const float* conv_b   = (const float*)d_in[5];
    const float* cond_w   = (const float*)d_in[6];
    const float* out_w    = (const float*)d_in[7];
    const float* out_b    = (const float*)d_in[8];
    const float* skip_w   = (const float*)d_in[9];
    const float* skip_b   = (const float*)d_in[10];
    const float* last1_w  = (const float*)d_in[11];
    const float* last1_b  = (const float*)d_in[12];
    const float* last2_w  = (const float*)d_in[13];
    const float* last2_b  = (const float*)d_in[14];
    const float* conv_in_w= (const float*)d_in[15];
    const float* up_w0    = (const float*)d_in[16];
    const float* up_w1    = (const float*)d_in[17];
    float* out = (float*)d_out;

    int dev = 0;
    cudaGetDevice(&dev);
    int sms = 148;
    cudaDeviceGetAttribute(&sms, cudaDevAttrMultiProcessorCount, dev);

    cudaFuncSetAttribute(first_kernel, cudaFuncAttributeMaxDynamicSharedMemorySize, 131072);
    cudaFuncSetAttribute(layer_kernel, cudaFuncAttributeMaxDynamicSharedMemorySize, 226304);
    cudaFuncSetAttribute(last_kernel,  cudaFuncAttributeMaxDynamicSharedMemorySize, 114688);

    /* weight prep */
    {
        int total = LAYERS * LAYER_WSZ;
        prep_layers_kernel<<<(total + 255) / 256, 256>>>(
            conv_w, conv_b, cond_w, out_w, out_b, skip_w, skip_b);
        prep_firstlast_kernel<<<(16384 + 4096 + 16384 + 255) / 256, 256>>>(
            first_w, last1_w, last2_w);
    }

    /* conditioning: 1x1 conv + two upsample stages */
    {
        int n1 = B_SZ * CCH * 400;
        convin_kernel<<<(n1 + 255) / 256, 256>>>(c, conv_in_w);

        float* c1p = nullptr; float* c2p = nullptr; float* cupp = nullptr;
        cudaGetSymbolAddress((void**)&c1p, g_c1);
        cudaGetSymbolAddress((void**)&c2p, g_c2);
        cudaGetSymbolAddress((void**)&cupp, g_cup);

        int n2 = B_SZ * CCH * 4000;
        upsample_kernel<<<(n2 + 255) / 256, 256>>>(c1p, up_w0, c2p, 400, 4000, 10, 21);
        int n3 = B_SZ * CCH * TLEN;
        upsample_kernel<<<(n3 + 255) / 256, 256>>>(c2p, up_w1, cupp, 4000, TLEN, 8, 17);
    }

    /* first conv */
    first_kernel<<<sms, 256, 131072>>>(x, first_b);

    /* 30 residual layers, ping-pong h */
    for (int l = 0; l < LAYERS; ++l) {
        int d = 1 << (l % 10);
        layer_kernel<<<sms, 256, 226304>>>(l, d, l & 1, l == 0 ? 1 : 0);
    }

    /* final projection */
    last_kernel<<<sms, 256, 114688>>>(last1_b, last2_b, out);
}

// round 2
// speedup vs baseline: 1.1682x; 1.1682x over previous
#include <cuda_runtime.h>
#include <math.h>

#define LAYERS 30
#define B_SZ 4
#define TLEN 32000
#define TT 64
#define NTILES (B_SZ * (TLEN / TT))   /* 2000 */
#define CH 64
#define GCH 128
#define CCH 80

/* packed per-layer weight blob (floats), all matrices transposed to [c][o] */
#define LAYER_WSZ 35072
#define OFF_WT1   8192
#define OFF_WTC   16384
#define OFF_WZ    26624
#define OFF_BCONV 34816
#define OFF_BSK   34944
#define OFF_BOUT  35008

typedef unsigned long long u64;

/* scratch (device globals: allocation-free rule) */
__device__ float g_h[2][B_SZ * CH * TLEN];      /* ping-pong residual */
__device__ float g_skips[B_SZ * CH * TLEN];
__device__ float g_c1[B_SZ * CCH * 400];
__device__ float g_c2[B_SZ * CCH * 4000];
__device__ float g_cup[B_SZ * CCH * TLEN];
__device__ float g_wt[LAYERS * LAYER_WSZ];
__device__ float g_wfirstT[256 * 64];
__device__ float g_wl1T[64 * 64];
__device__ float g_wl2T[64 * 256];

__device__ __forceinline__ float sig_f(float v) {
    return __fdividef(1.f, 1.f + __expf(-v));
}
__device__ __forceinline__ float tanh_f(float v) {
    return __fdividef(2.f, 1.f + __expf(-2.f * v)) - 1.f;
}

/* ---- packed f32x2 helpers (FFMA2: 2 MACs per fma-pipe issue) ---- */
__device__ __forceinline__ u64 pk2(float lo, float hi) {
    u64 r; asm("mov.b64 %0, {%1, %2};" : "=l"(r) : "f"(lo), "f"(hi)); return r;
}
__device__ __forceinline__ u64 dup2f(float v) { return pk2(v, v); }
__device__ __forceinline__ void fma2(u64& d, u64 a, u64 b) {
    asm("fma.rn.f32x2 %0, %1, %2, %0;" : "+l"(d) : "l"(a), "l"(b));
}
__device__ __forceinline__ void upk(float& lo, float& hi, u64 v) {
    asm("mov.b64 {%0, %1}, %2;" : "=f"(lo), "=f"(hi) : "l"(v));
}

/* ------------------- weight prep: transpose/pack, coalesced layer loads ----- */
__global__ void prep_layers_kernel(const float* __restrict__ conv_w,
                                   const float* __restrict__ conv_b,
                                   const float* __restrict__ cond_w,
                                   const float* __restrict__ out_w,
                                   const float* __restrict__ out_b,
                                   const float* __restrict__ skip_w,
                                   const float* __restrict__ skip_b) {
    int idx = blockIdx.x * blockDim.x + threadIdx.x;
    if (idx >= LAYERS * LAYER_WSZ) return;
    int l = idx / LAYER_WSZ;
    int j = idx % LAYER_WSZ;
    float v;
    if (j < OFF_WT1) {                       /* wt0[c][o] : delayed tap */
        int c = j >> 7, o = j & 127;
        v = conv_w[((l * 128 + o) * 64 + c) * 2 + 0];
    } else if (j < OFF_WTC) {                /* wt1[c][o] : current tap */
        int jj = j - OFF_WT1; int c = jj >> 7, o = jj & 127;
        v = conv_w[((l * 128 + o) * 64 + c) * 2 + 1];
    } else if (j < OFF_WZ) {                 /* wtc[c][o] : cond */
        int jj = j - OFF_WTC; int c = jj >> 7, o = jj & 127;
        v = cond_w[(l * 128 + o) * 80 + c];
    } else if (j < OFF_BCONV) {              /* wz[c][o2] : skip(0..63)|out(64..127) */
        int jj = j - OFF_WZ; int c = jj >> 7, o2 = jj & 127;
        v = (o2 < 64) ? skip_w[(l * 64 + o2) * 64 + c]
                      : out_w[(l * 64 + (o2 - 64)) * 64 + c];
    } else if (j < OFF_BSK) {
        v = conv_b[l * 128 + (j - OFF_BCONV)];
    } else if (j < OFF_BOUT) {
        v = skip_b[l * 64 + (j - OFF_BSK)];
    } else {
        v = out_b[l * 64 + (j - OFF_BOUT)];
    }
    g_wt[idx] = v;
}

__global__ void prep_firstlast_kernel(const float* __restrict__ first_w,
                                      const float* __restrict__ last1_w,
                                      const float* __restrict__ last2_w) {
    int idx = blockIdx.x * blockDim.x + threadIdx.x;
    if (idx < 16384) {                                   /* firstT[c][o], c<256,o<64 */
        int c = idx >> 6, o = idx & 63;
        g_wfirstT[idx] = first_w[o * 256 + c];
    } else if (idx < 16384 + 4096) {                     /* l1T[c][o] 64x64 */
        int jj = idx - 16384; int c = jj >> 6, o = jj & 63;
        g_wl1T[jj] = last1_w[o * 64 + c];
    } else if (idx < 16384 + 4096 + 16384) {             /* l2T[c][o] 64x256 */
        int jj = idx - 16384 - 4096; int c = jj >> 8, o = jj & 255;
        g_wl2T[jj] = last2_w[o * 64 + c];
    }
}

/* ------------------- conditioning network ---------------------------------- */
__global__ void convin_kernel(const float* __restrict__ cin,
                              const float* __restrict__ w) {
    int idx = blockIdx.x * blockDim.x + threadIdx.x;
    if (idx >= B_SZ * CCH * 400) return;
    int f = idx % 400;
    int o = (idx / 400) % CCH;
    int b = idx / (400 * CCH);
    const float* src = cin + (b * CCH) * 400 + f;
    float acc = 0.f;
#pragma unroll 8
    for (int c = 0; c < 80; ++c)
        acc += __ldg(&w[o * 80 + c]) * src[c * 400];
    g_c1[idx] = acc;
}

/* nearest-repeat by `scale` then depthwise conv (K=2*scale+1, zero pad scale) */
__global__ void upsample_kernel(const float* __restrict__ src,
                                const float* __restrict__ w,
                                float* __restrict__ dst,
                                int srcT, int dstT, int scale, int K) {
    int idx = blockIdx.x * blockDim.x + threadIdx.x;
    if (idx >= B_SZ * CCH * dstT) return;
    int t = idx % dstT;
    int ch = (idx / dstT) % CCH;
    int b = idx / (dstT * CCH);
    const float* s = src + (b * CCH + ch) * srcT;
    int base = t - scale;
    float acc = 0.f;
    for (int j = 0; j < K; ++j) {
        int u = base + j;
        if (u >= 0 && u < dstT) acc += __ldg(&w[j]) * s[u / scale];
    }
    dst[idx] = acc;
}

/* ------------------- first 1x1 conv: h = first_w @ x + b ------------------- */
__global__ void __launch_bounds__(256) first_kernel(const float* __restrict__ x,
                                                    const float* __restrict__ first_b) {
    extern __shared__ float sm[];
    float* xs = sm;            /* [256][64] */
    float* wf = sm + 16384;    /* wfT[c][o] 256x64 */
    for (int i = threadIdx.x; i < 16384 / 4; i += blockDim.x)
        ((float4*)wf)[i] = ((const float4*)g_wfirstT)[i];

    int to = threadIdx.x & 15, oo = threadIdx.x >> 4;
    int tb = to * 4, ob = oo * 4;

    for (int tile = blockIdx.x; tile < NTILES; tile += gridDim.x) {
        int b = tile / (TLEN / TT);
        int t0 = (tile % (TLEN / TT)) * TT;
        __syncthreads();
        const float* xb = x + (size_t)b * 256 * TLEN;
        for (int i = threadIdx.x; i < 256 * (TT / 4); i += blockDim.x) {
            int c = i / (TT / 4), q = i % (TT / 4);
            ((float4*)xs)[c * (TT / 4) + q] =
                *(const float4*)&xb[c * TLEN + t0 + q * 4];
        }
        __syncthreads();

        /* 2 output-pairs x 4 times, packed */
        u64 acc[2][4];
#pragma unroll
        for (int op = 0; op < 2; ++op) {
            u64 bv = pk2(first_b[ob + 2 * op], first_b[ob + 2 * op + 1]);
#pragma unroll
            for (int ti = 0; ti < 4; ++ti) acc[op][ti] = bv;
        }
#pragma unroll 2
        for (int c = 0; c < 256; ++c) {
            float4 xv4 = *(const float4*)(xs + c * TT + tb);
            u64 xv[4] = {dup2f(xv4.x), dup2f(xv4.y), dup2f(xv4.z), dup2f(xv4.w)};
            ulonglong2 wv = *(const ulonglong2*)(wf + c * 64 + ob);
            u64 w2[2] = {wv.x, wv.y};
#pragma unroll
            for (int op = 0; op < 2; ++op)
#pragma unroll
                for (int ti = 0; ti < 4; ++ti)
                    fma2(acc[op][ti], w2[op], xv[ti]);
        }
        float* hb = g_h[0] + (size_t)b * CH * TLEN;
#pragma unroll
        for (int op = 0; op < 2; ++op) {
            float lo[4], hi[4];
#pragma unroll
            for (int ti = 0; ti < 4; ++ti) upk(lo[ti], hi[ti], acc[op][ti]);
            float4 v0; v0.x = lo[0]; v0.y = lo[1]; v0.z = lo[2]; v0.w = lo[3];
            float4 v1; v1.x = hi[0]; v1.y = hi[1]; v1.z = hi[2]; v1.w = hi[3];
            *(float4*)&hb[(ob + 2 * op) * TLEN + t0 + tb] = v0;
            *(float4*)&hb[(ob + 2 * op + 1) * TLEN + t0 + tb] = v1;
        }
    }
}

/* ------------------- fused WaveNet residual layer -------------------------- */
__global__ void __launch_bounds__(256) layer_kernel(int l, int d, int hin, int first_layer) {
    extern __shared__ float sm[];
    float* sw = sm;                          /* 35072 packed weights */
    float* sh_cur = sm + LAYER_WSZ;          /* [64][TT] */
    float* sh_del = sh_cur + CH * TT;        /* [64][TT] */
    float* sc = sh_del + CH * TT;            /* [80][TT] */
    float* sg = sc + CCH * TT;               /* [128][TT]; rows 0..63 reused for z */

    const float* wt0 = sw;
    const float* wt1 = sw + OFF_WT1;
    const float* wtc = sw + OFF_WTC;
    const float* wz  = sw + OFF_WZ;
    const float* bconv = sw + OFF_BCONV;
    const float* bsk = sw + OFF_BSK;
    const float* bout = sw + OFF_BOUT;

    const float* wsrc = g_wt + (size_t)l * LAYER_WSZ;
    for (int i = threadIdx.x; i < LAYER_WSZ / 4; i += blockDim.x)
        ((float4*)sw)[i] = ((const float4*)wsrc)[i];

    const float* h_in = g_h[hin];
    float* h_out = g_h[hin ^ 1];

    int to = threadIdx.x & 15;   /* 16 time groups of 4 */
    int oo = threadIdx.x >> 4;   /* 16 out groups of 8  */
    int tb = to * 4, ob = oo * 8;

    for (int tile = blockIdx.x; tile < NTILES; tile += gridDim.x) {
        int b = tile / (TLEN / TT);
        int t0 = (tile % (TLEN / TT)) * TT;
        __syncthreads();   /* protect smem from previous iteration readers */

        const float* hb = h_in + (size_t)b * CH * TLEN;
        for (int i = threadIdx.x; i < CH * (TT / 4); i += blockDim.x) {
            int c = i / (TT / 4), q = i % (TT / 4);
            ((float4*)sh_cur)[c * (TT / 4) + q] =
                *(const float4*)&hb[c * TLEN + t0 + q * 4];
        }
        for (int i = threadIdx.x; i < CH * TT; i += blockDim.x) {
            int c = i >> 6, tt = i & 63;
            int t = t0 + tt - d;
            sh_del[c * TT + tt] = (t >= 0) ? hb[c * TLEN + t] : 0.f;
        }
        const float* cb = g_cup + (size_t)b * CCH * TLEN;
        for (int i = threadIdx.x; i < CCH * (TT / 4); i += blockDim.x) {
            int c = i / (TT / 4), q = i % (TT / 4);
            ((float4*)sc)[c * (TT / 4) + q] =
                *(const float4*)&cb[c * TLEN + t0 + q * 4];
        }
        __syncthreads();

        /* ---- gate GEMM: g[128][TT] = W0*h(t-d) + W1*h(t) + Wc*c + b ----
           4 output-pairs x 4 times, packed f32x2 */
        u64 acc[4][4];
#pragma unroll
        for (int op = 0; op < 4; ++op) {
            u64 bv = pk2(bconv[ob + 2 * op], bconv[ob + 2 * op + 1]);
#pragma unroll
            for (int ti = 0; ti < 4; ++ti) acc[op][ti] = bv;
        }
#pragma unroll 2
        for (int c = 0; c < 64; ++c) {
            float4 hd4 = *(const float4*)(sh_del + c * TT + tb);
            float4 hc4 = *(const float4*)(sh_cur + c * TT + tb);
            u64 hd[4] = {dup2f(hd4.x), dup2f(hd4.y), dup2f(hd4.z), dup2f(hd4.w)};
            u64 hc[4] = {dup2f(hc4.x), dup2f(hc4.y), dup2f(hc4.z), dup2f(hc4.w)};
            ulonglong2 w0a = *(const ulonglong2*)(wt0 + c * 128 + ob);
            ulonglong2 w0b = *(const ulonglong2*)(wt0 + c * 128 + ob + 4);
            ulonglong2 w1a = *(const ulonglong2*)(wt1 + c * 128 + ob);
            ulonglong2 w1b = *(const ulonglong2*)(wt1 + c * 128 + ob + 4);
            u64 w0[4] = {w0a.x, w0a.y, w0b.x, w0b.y};
            u64 w1[4] = {w1a.x, w1a.y, w1b.x, w1b.y};
#pragma unroll
            for (int op = 0; op < 4; ++op)
#pragma unroll
                for (int ti = 0; ti < 4; ++ti) {
                    fma2(acc[op][ti], w0[op], hd[ti]);
                    fma2(acc[op][ti], w1[op], hc[ti]);
                }
        }
#pragma unroll 2
        for (int c = 0; c < 80; ++c) {
            float4 cv4 = *(const float4*)(sc + c * TT + tb);
            u64 cv[4] = {dup2f(cv4.x), dup2f(cv4.y), dup2f(cv4.z), dup2f(cv4.w)};
            ulonglong2 wa = *(const ulonglong2*)(wtc + c * 128 + ob);
            ulonglong2 wb = *(const ulonglong2*)(wtc + c * 128 + ob + 4);
            u64 w2[4] = {wa.x, wa.y, wb.x, wb.y};
#pragma unroll
            for (int op = 0; op < 4; ++op)
#pragma unroll
                for (int ti = 0; ti < 4; ++ti)
                    fma2(acc[op][ti], w2[op], cv[ti]);
        }
#pragma unroll
        for (int op = 0; op < 4; ++op) {
            float lo[4], hi[4];
#pragma unroll
            for (int ti = 0; ti < 4; ++ti) upk(lo[ti], hi[ti], acc[op][ti]);
            float4 v0; v0.x = lo[0]; v0.y = lo[1]; v0.z = lo[2]; v0.w = lo[3];
            float4 v1; v1.x = hi[0]; v1.y = hi[1]; v1.z = hi[2]; v1.w = hi[3];
            *(float4*)(sg + (ob + 2 * op) * TT + tb) = v0;
            *(float4*)(sg + (ob + 2 * op + 1) * TT + tb) = v1;
        }
        __syncthreads();

        /* ---- z = tanh(a) * sigmoid(b), in place over rows 0..63 ---- */
        {
            int o = threadIdx.x >> 2;
            int ts = (threadIdx.x & 3) * 16;
#pragma unroll
            for (int k = 0; k < 16; k += 4) {
                float4 a4 = *(const float4*)(sg + o * TT + ts + k);
                float4 b4 = *(const float4*)(sg + (o + 64) * TT + ts + k);
                float4 z4;
                z4.x = tanh_f(a4.x) * sig_f(b4.x);
                z4.y = tanh_f(a4.y) * sig_f(b4.y);
                z4.z = tanh_f(a4.z) * sig_f(b4.z);
                z4.w = tanh_f(a4.w) * sig_f(b4.w);
                *(float4*)(sg + o * TT + ts + k) = z4;
            }
        }
        __syncthreads();

        /* ---- skip/out GEMM: [skip;out][128] x z[64], packed ---- */
#pragma unroll
        for (int op = 0; op < 4; ++op) {
            int o2 = ob + 2 * op;
            u64 bv = (o2 < 64) ? pk2(bsk[o2], bsk[o2 + 1])
                               : pk2(bout[o2 - 64], bout[o2 - 63]);
#pragma unroll
            for (int ti = 0; ti < 4; ++ti) acc[op][ti] = bv;
        }
#pragma unroll 2
        for (int c = 0; c < 64; ++c) {
            float4 zv4 = *(const float4*)(sg + c * TT + tb);
            u64 zv[4] = {dup2f(zv4.x), dup2f(zv4.y), dup2f(zv4.z), dup2f(zv4.w)};
            ulonglong2 wa = *(const ulonglong2*)(wz + c * 128 + ob);
            ulonglong2 wb = *(const ulonglong2*)(wz + c * 128 + ob + 4);
            u64 w2[4] = {wa.x, wa.y, wb.x, wb.y};
#pragma unroll
            for (int op = 0; op < 4; ++op)
#pragma unroll
                for (int ti = 0; ti < 4; ++ti)
                    fma2(acc[op][ti], w2[op], zv[ti]);
        }

        if (ob < 64) {  /* skip accumulation */
            float* skb = g_skips + (size_t)b * CH * TLEN;
#pragma unroll
            for (int op = 0; op < 4; ++op) {
                float lo[4], hi[4];
#pragma unroll
                for (int ti = 0; ti < 4; ++ti) upk(lo[ti], hi[ti], acc[op][ti]);
                float* p0 = skb + (ob + 2 * op) * TLEN + t0 + tb;
                float* p1 = skb + (ob + 2 * op + 1) * TLEN + t0 + tb;
                float4 v0; v0.x = lo[0]; v0.y = lo[1]; v0.z = lo[2]; v0.w = lo[3];
                float4 v1; v1.x = hi[0]; v1.y = hi[1]; v1.z = hi[2]; v1.w = hi[3];
                if (!first_layer) {
                    float4 o0 = *(const float4*)p0;
                    float4 o1 = *(const float4*)p1;
                    v0.x += o0.x; v0.y += o0.y; v0.z += o0.z; v0.w += o0.w;
                    v1.x += o1.x; v1.y += o1.y; v1.z += o1.z; v1.w += o1.w;
                }
                *(float4*)p0 = v0;
                *(float4*)p1 = v1;
            }
        } else {        /* residual update h_out = h_in + out */
            float* hob = h_out + (size_t)b * CH * TLEN;
#pragma unroll
            for (int op = 0; op < 4; ++op) {
                float lo[4], hi[4];
#pragma unroll
                for (int ti = 0; ti < 4; ++ti) upk(lo[ti], hi[ti], acc[op][ti]);
                int o0 = ob - 64 + 2 * op;
                float4 r0 = *(const float4*)(sh_cur + o0 * TT + tb);
                float4 r1 = *(const float4*)(sh_cur + (o0 + 1) * TT + tb);
                float4 v0; v0.x = lo[0] + r0.x; v0.y = lo[1] + r0.y;
                v0.z = lo[2] + r0.z; v0.w = lo[3] + r0.w;
                float4 v1; v1.x = hi[0] + r1.x; v1.y = hi[1] + r1.y;
                v1.z = hi[2] + r1.z; v1.w = hi[3] + r1.w;
                *(float4*)&hob[o0 * TLEN + t0 + tb] = v0;
                *(float4*)&hob[(o0 + 1) * TLEN + t0 + tb] = v1;
            }
        }
    }
}

/* ------------------- last: relu -> 1x1(64) -> relu -> 1x1(256) ------------- */
__global__ void __launch_bounds__(256) last_kernel(const float* __restrict__ l1b,
                                                   const float* __restrict__ l2b,
                                                   float* __restrict__ out) {
    extern __shared__ float sm[];
    float* w1 = sm;             /* 64x64  l1T[c][o] */
    float* w2 = sm + 4096;      /* 64x256 l2T[c][o] */
    float* sk = sm + 20480;     /* [64][TT] */
    float* o1 = sm + 24576;     /* [64][TT] */

    for (int i = threadIdx.x; i < 4096 / 4; i += blockDim.x)
        ((float4*)w1)[i] = ((const float4*)g_wl1T)[i];
    for (int i = threadIdx.x; i < 16384 / 4; i += blockDim.x)
        ((float4*)w2)[i] = ((const float4*)g_wl2T)[i];

    int to = threadIdx.x & 15, oo = threadIdx.x >> 4;
    int tb = to * 4;

    for (int tile = blockIdx.x; tile < NTILES; tile += gridDim.x) {
        int b = tile / (TLEN / TT);
        int t0 = (tile % (TLEN / TT)) * TT;
        __syncthreads();
        const float* skb = g_skips + (size_t)b * CH * TLEN;
        for (int i = threadIdx.x; i < CH * (TT / 4); i += blockDim.x) {
            int c = i / (TT / 4), q = i % (TT / 4);
            float4 v = *(const float4*)&skb[c * TLEN + t0 + q * 4];
            v.x = fmaxf(v.x, 0.f); v.y = fmaxf(v.y, 0.f);
            v.z = fmaxf(v.z, 0.f); v.w = fmaxf(v.w, 0.f);
            ((float4*)sk)[c * (TT / 4) + q] = v;
        }
        __syncthreads();

        /* GEMM1: 64x64, relu */
        {
            int ob = oo * 4;
            u64 acc[2][4];
#pragma unroll
            for (int op = 0; op < 2; ++op) {
                u64 bv = pk2(l1b[ob + 2 * op], l1b[ob + 2 * op + 1]);
#pragma unroll
                for (int ti = 0; ti < 4; ++ti) acc[op][ti] = bv;
            }
#pragma unroll 2
            for (int c = 0; c < 64; ++c) {
                float4 xv4 = *(const float4*)(sk + c * TT + tb);
                u64 xv[4] = {dup2f(xv4.x), dup2f(xv4.y), dup2f(xv4.z), dup2f(xv4.w)};
                ulonglong2 wv = *(const ulonglong2*)(w1 + c * 64 + ob);
                u64 wp[2] = {wv.x, wv.y};
#pragma unroll
                for (int op = 0; op < 2; ++op)
#pragma unroll
                    for (int ti = 0; ti < 4; ++ti)
                        fma2(acc[op][ti], wp[op], xv[ti]);
            }
#pragma unroll
            for (int op = 0; op < 2; ++op) {
                float lo[4], hi[4];
#pragma unroll
                for (int ti = 0; ti < 4; ++ti) upk(lo[ti], hi[ti], acc[op][ti]);
                float4 v0, v1;
                v0.x = fmaxf(lo[0], 0.f); v0.y = fmaxf(lo[1], 0.f);
                v0.z = fmaxf(lo[2], 0.f); v0.w = fmaxf(lo[3], 0.f);
                v1.x = fmaxf(hi[0], 0.f); v1.y = fmaxf(hi[1], 0.f);
                v1.z = fmaxf(hi[2], 0.f); v1.w = fmaxf(hi[3], 0.f);
                *(float4*)(o1 + (ob + 2 * op) * TT + tb) = v0;
                *(float4*)(o1 + (ob + 2 * op + 1) * TT + tb) = v1;
            }
        }
        __syncthreads();

        /* GEMM2: 256x64, two halves of 128 outputs */
        float* ob_out = out + (size_t)b * 256 * TLEN;
#pragma unroll
        for (int half = 0; half < 2; ++half) {
            int ob2 = half * 128 + oo * 8;
            u64 acc[4][4];
#pragma unroll
            for (int op = 0; op < 4; ++op) {
                u64 bv = pk2(l2b[ob2 + 2 * op], l2b[ob2 + 2 * op + 1]);
#pragma unroll
                for (int ti = 0; ti < 4; ++ti) acc[op][ti] = bv;
            }
#pragma unroll 2
            for (int c = 0; c < 64; ++c) {
                float4 zv4 = *(const float4*)(o1 + c * TT + tb);
                u64 zv[4] = {dup2f(zv4.x), dup2f(zv4.y), dup2f(zv4.z), dup2f(zv4.w)};
                ulonglong2 wa = *(const ulonglong2*)(w2 + c * 256 + ob2);
                ulonglong2 wb = *(const ulonglong2*)(w2 + c * 256 + ob2 + 4);
                u64 wp[4] = {wa.x, wa.y, wb.x, wb.y};
#pragma unroll
                for (int op = 0; op < 4; ++op)
#pragma unroll
                    for (int ti = 0; ti < 4; ++ti)
                        fma2(acc[op][ti], wp[op], zv[ti]);
            }
#pragma unroll
            for (int op = 0; op < 4; ++op) {
                float lo[4], hi[4];
#pragma unroll
                for (int ti = 0; ti < 4; ++ti) upk(lo[ti], hi[ti], acc[op][ti]);
                float4 v0; v0.x = lo[0]; v0.y = lo[1]; v0.z = lo[2]; v0.w = lo[3];
                float4 v1; v1.x = hi[0]; v1.y = hi[1]; v1.z = hi[2]; v1.w = hi[3];
                *(float4*)&ob_out[(ob2 + 2 * op) * TLEN + t0 + tb] = v0;
                *(float4*)&ob_out[(ob2 + 2 * op + 1) * TLEN + t0 + tb] = v1;
            }
        }
    }
}

/* --------------------------------------------------------------------------- */
extern "C" void kernel_launch(void* const* d_in, const int* in_sizes, int n_in,
                              void* d_out, int out_size) {
    const float* x        = (const float*)d_in[0];
    const float* c        = (const float*)d_in[1];
    const float* first_w  = (const float*)d_in[2];
    const float* first_b  = (const float*)d_in[3];
    const float* conv_w   = (const float*)d_in[4];
    const float* conv_b   = (const float*)d_in[5];
    const float* cond_w   = (const float*)d_in[6];
    const float* out_w    = (const float*)d_in[7];
    const float* out_b    = (const float*)d_in[8];
    const float* skip_w   = (const float*)d_in[9];
    const float* skip_b   = (const float*)d_in[10];
    const float* last1_w  = (const float*)d_in[11];
    const float* last1_b  = (const float*)d_in[12];
    const float* last2_w  = (const float*)d_in[13];
    const float* last2_b  = (const float*)d_in[14];
    const float* conv_in_w= (const float*)d_in[15];
    const float* up_w0    = (const float*)d_in[16];
    const float* up_w1    = (const float*)d_in[17];
    float* out = (float*)d_out;

    int dev = 0;
    cudaGetDevice(&dev);
    int sms = 148;
    cudaDeviceGetAttribute(&sms, cudaDevAttrMultiProcessorCount, dev);

    cudaFuncSetAttribute(first_kernel, cudaFuncAttributeMaxDynamicSharedMemorySize, 131072);
    cudaFuncSetAttribute(layer_kernel, cudaFuncAttributeMaxDynamicSharedMemorySize, 226304);
    cudaFuncSetAttribute(last_kernel,  cudaFuncAttributeMaxDynamicSharedMemorySize, 114688);

    /* weight prep */
    {
        int total = LAYERS * LAYER_WSZ;
        prep_layers_kernel<<<(total + 255) / 256, 256>>>(
            conv_w, conv_b, cond_w, out_w, out_b, skip_w, skip_b);
        prep_firstlast_kernel<<<(16384 + 4096 + 16384 + 255) / 256, 256>>>(
            first_w, last1_w, last2_w);
    }

    /* conditioning: 1x1 conv + two upsample stages */
    {
        int n1 = B_SZ * CCH * 400;
        convin_kernel<<<(n1 + 255) / 256, 256>>>(c, conv_in_w);

        float* c1p = nullptr; float* c2p = nullptr; float* cupp = nullptr;
        cudaGetSymbolAddress((void**)&c1p, g_c1);
        cudaGetSymbolAddress((void**)&c2p, g_c2);
        cudaGetSymbolAddress((void**)&cupp, g_cup);

        int n2 = B_SZ * CCH * 4000;
        upsample_kernel<<<(n2 + 255) / 256, 256>>>(c1p, up_w0, c2p, 400, 4000, 10, 21);
        int n3 = B_SZ * CCH * TLEN;
        upsample_kernel<<<(n3 + 255) / 256, 256>>>(c2p, up_w1, cupp, 4000, TLEN, 8, 17);
    }

    /* first conv */
    first_kernel<<<sms, 256, 131072>>>(x, first_b);

    /* 30 residual layers, ping-pong h */
    for (int l = 0; l < LAYERS; ++l) {
        int d = 1 << (l % 10);
        layer_kernel<<<sms, 256, 226304>>>(l, d, l & 1, l == 0 ? 1 : 0);
    }

    /* final projection */
    last_kernel<<<sms, 256, 114688>>>(last1_b, last2_b, out);
}